// round 3
// baseline (speedup 1.0000x reference)
#include <cuda_runtime.h>
#include <cuda_bf16.h>

// QSplitIntSoftmax: integer-softmax with threshold-split dual quantization.
// x: (2,16,1024,1024) fp32 -> 32768 rows of N=1024.
// One WARP per row: 32 lanes x 8 float4 = 1024 elems held in registers.
// 256-thread CTAs handle 8 rows; no shared memory, no block barriers.
// launch_bounds(256,2): avoid forced 64-reg cap -> no local-memory spills.

#define ROW_N        1024
#define THREADS      256
#define ROWS_PER_CTA 8
#define V4_PER_LANE  8   // 8 float4 = 32 elems per lane

__global__ __launch_bounds__(THREADS, 2)
void qsplit_int_softmax_kernel(const float* __restrict__ x,
                               const float* __restrict__ scale_p,
                               const float* __restrict__ thr_p,
                               float* __restrict__ out,
                               int rows)
{
    const int lane = threadIdx.x & 31;
    const int wid  = threadIdx.x >> 5;
    const long long row = (long long)blockIdx.x * ROWS_PER_CTA + wid;
    if (row >= rows) return;

    const float sf  = __ldg(scale_p);
    const float thr = __ldg(thr_p);

    // ---- scalar constants, matching JAX f32 weak-type semantics ----
    const float x0_int = floorf(__fdiv_rn(-0.69314718f, sf));             // -14 @ sf=0.05
    const float clampv = __fmul_rn(15.0f, x0_int);                        // n * x0_int
    const float b_int  = floorf(__fdiv_rn((float)(0.96963238 / 0.35815147), sf));
    const float sf2    = __fmul_rn(sf, sf);
    const float c_int  = floorf(__fdiv_rn((float)(1.0 / 0.35815147), sf2));

    const float oA      = __fdiv_rn(thr, 255.0f);                         // threshold / 255
    const float denomA  = __fmul_rn(4294967296.0f, oA);                   // f32(2^32)*oA
    const float invDenA = __fdiv_rn(1.0f, denomA);
    const float invDenB = __fdiv_rn(1.0f, (float)(4294967296.0 / 255.0));
    const float oB      = (float)(1.0 / 255.0);
    const float thr_fl  = floorf(__fmul_rn(thr, 256.0f));                 // floor(thr*2^8)

    // ---- load full row: 8 coalesced float4 per lane (front-batched, MLP=8) ----
    const float4* __restrict__ xr = reinterpret_cast<const float4*>(x + row * ROW_N);
    float4 v[V4_PER_LANE];
#pragma unroll
    for (int j = 0; j < V4_PER_LANE; j++)
        v[j] = xr[j * 32 + lane];

    // x_int = x / sf  (exact IEEE division, matching reference)
    float val[32];
#pragma unroll
    for (int j = 0; j < V4_PER_LANE; j++) {
        val[4*j + 0] = __fdiv_rn(v[j].x, sf);
        val[4*j + 1] = __fdiv_rn(v[j].y, sf);
        val[4*j + 2] = __fdiv_rn(v[j].z, sf);
        val[4*j + 3] = __fdiv_rn(v[j].w, sf);
    }

    // ---- row max (local tree + 5-step warp bfly; order-independent) ----
    float m = val[0];
#pragma unroll
    for (int i = 1; i < 32; i++) m = fmaxf(m, val[i]);
#pragma unroll
    for (int o = 16; o > 0; o >>= 1)
        m = fmaxf(m, __shfl_xor_sync(0xffffffffu, m, o));

    // ---- integer exp per element + local sum (in-place over val[]) ----
    float lsum = 0.0f;
#pragma unroll
    for (int i = 0; i < 32; i++) {
        float t = fmaxf(__fadd_rn(val[i], -m), clampv);       // clamp at n*x0_int
        float q = floorf(__fdiv_rn(t, x0_int));               // EXACT div: bit-matches ref
        float r = __fadd_rn(t, -__fmul_rn(x0_int, q));        // t - x0_int*q
        float z = __fadd_rn(__fmul_rn(r, __fadd_rn(r, b_int)), c_int);
        int   k = 15 - (int)q;                                // q in [0,15] exactly
        float p2 = __int_as_float((127 + k) << 23);           // 2^(15-q), exact
        float ei = fmaxf(floorf(__fmul_rn(z, p2)), 0.0f);
        val[i] = ei;
        lsum = __fadd_rn(lsum, ei);
    }

    // ---- row sum (5-step warp bfly) ----
#pragma unroll
    for (int o = 16; o > 0; o >>= 1)
        lsum = __fadd_rn(lsum, __shfl_xor_sync(0xffffffffu, lsum, o));

    const float factor = floorf(__fdiv_rn(4294967296.0f, lsum));
    // approx_threshold = floor(thr*256) * sum / 256 ; /256 exact -> *2^-8
    const float approx = __fmul_rn(__fmul_rn(thr_fl, lsum), 0.00390625f);

    // ---- quantized split output ----
    float4* __restrict__ orow = reinterpret_cast<float4*>(out + row * ROW_N);
#pragma unroll
    for (int j = 0; j < V4_PER_LANE; j++) {
        float4 o4;
        float* op = &o4.x;
#pragma unroll
        for (int c = 0; c < 4; c++) {
            const float e  = val[4*j + c];
            const float ef = __fmul_rn(e, factor);
            float rA = __fmul_rn(floorf(__fmul_rn(ef, invDenA)), oA);
            float rB = __fmul_rn(fminf(floorf(__fmul_rn(ef, invDenB)), 255.0f), oB);
            op[c] = (e <= approx) ? rA : rB;
        }
        orow[j * 32 + lane] = o4;
    }
}

extern "C" void kernel_launch(void* const* d_in, const int* in_sizes, int n_in,
                              void* d_out, int out_size)
{
    const float* x     = (const float*)d_in[0];
    const float* scale = (const float*)d_in[1];
    const float* thr   = (const float*)d_in[2];
    float* out         = (float*)d_out;

    const int rows = in_sizes[0] / ROW_N;                     // 32768
    const int ctas = (rows + ROWS_PER_CTA - 1) / ROWS_PER_CTA;
    qsplit_int_softmax_kernel<<<ctas, THREADS>>>(x, scale, thr, out, rows);
}

// round 14
// speedup vs baseline: 1.8862x; 1.8862x over previous
#include <cuda_runtime.h>
#include <cuda_bf16.h>

// QSplitIntSoftmax: integer-softmax with threshold-split dual quantization.
// x: (2,16,1024,1024) fp32 -> 32768 rows of N=1024.
// One WARP per row: 32 lanes x 8 float4 = 1024 elems held in registers.
// R3 (88.5us, DRAM 33%, issue-bound on IEEE divs) -> this kernel:
//   * per-element divisions -> reciprocal multiplies (+ IMAD-built 2^(15-q))
//   * CTA 256 -> 128 threads: finer reg-alloc granularity, 16 -> ~20-24 warps/SM
//   * streaming cache hints (no reuse in a 256MB stream)
//   * epilogue: select (invDen, scale, cap) BEFORE quantizing -- bit-identical
//     to computing both branches (fminf(x,+INF)==x), saves 1 FRND + 1 FMUL/elem

#define ROW_N        1024
#define THREADS      128
#define ROWS_PER_CTA 4
#define V4_PER_LANE  8   // 8 float4 = 32 elems per lane

__global__ __launch_bounds__(THREADS)
void qsplit_int_softmax_kernel(const float* __restrict__ x,
                               const float* __restrict__ scale_p,
                               const float* __restrict__ thr_p,
                               float* __restrict__ out,
                               int rows)
{
    const int lane = threadIdx.x & 31;
    const int wid  = threadIdx.x >> 5;
    const long long row = (long long)blockIdx.x * ROWS_PER_CTA + wid;
    if (row >= rows) return;

    const float sf  = __ldg(scale_p);
    const float thr = __ldg(thr_p);

    // ---- scalar constants (exact divs here are per-row, off the hot path) ----
    const float x0_int = floorf(__fdiv_rn(-0.69314718f, sf));             // -14 @ sf=0.05
    const float clampv = __fmul_rn(15.0f, x0_int);                        // n * x0_int
    const float b_int  = floorf(__fdiv_rn((float)(0.96963238 / 0.35815147), sf));
    const float sf2    = __fmul_rn(sf, sf);
    const float c_int  = floorf(__fdiv_rn((float)(1.0 / 0.35815147), sf2));
    const float inv_sf = __fdiv_rn(1.0f, sf);                             // 20.0f exactly @0.05
    const float inv_x0 = __fdiv_rn(1.0f, x0_int);

    const float oA      = __fdiv_rn(thr, 255.0f);                         // threshold / 255
    const float denomA  = __fmul_rn(4294967296.0f, oA);                   // f32(2^32)*oA
    const float invDenA = __fdiv_rn(1.0f, denomA);
    const float invDenB = __fdiv_rn(1.0f, (float)(4294967296.0 / 255.0));
    const float oB      = (float)(1.0 / 255.0);
    const float thr_fl  = floorf(__fmul_rn(thr, 256.0f));                 // floor(thr*2^8)
    const float posInf  = __int_as_float(0x7f800000);                     // +INF (A: no clamp)

    // ---- load full row: 8 coalesced float4 per lane (front-batched, MLP=8) ----
    const float4* __restrict__ xr = reinterpret_cast<const float4*>(x + row * ROW_N);
    float val[32];
#pragma unroll
    for (int j = 0; j < V4_PER_LANE; j++) {
        const float4 v = __ldcs(&xr[j * 32 + lane]);          // streaming: no L2 reuse
        val[4*j + 0] = __fmul_rn(v.x, inv_sf);
        val[4*j + 1] = __fmul_rn(v.y, inv_sf);
        val[4*j + 2] = __fmul_rn(v.z, inv_sf);
        val[4*j + 3] = __fmul_rn(v.w, inv_sf);
    }

    // ---- row max (local tree + 5-step warp bfly; order-independent) ----
    float m = val[0];
#pragma unroll
    for (int i = 1; i < 32; i++) m = fmaxf(m, val[i]);
#pragma unroll
    for (int o = 16; o > 0; o >>= 1)
        m = fmaxf(m, __shfl_xor_sync(0xffffffffu, m, o));

    // ---- integer exp per element + local sum (in-place over val[]) ----
    float lsum = 0.0f;
#pragma unroll
    for (int i = 0; i < 32; i++) {
        float t = fmaxf(__fadd_rn(val[i], -m), clampv);       // clamp at n*x0_int
        float q = floorf(__fmul_rn(t, inv_x0));               // floor(t / x0_int)
        float r = __fmaf_rn(-x0_int, q, t);                   // t - x0_int*q (exact: small ints)
        float z = __fadd_rn(__fmul_rn(r, __fadd_rn(r, b_int)), c_int);
        int  qi = (int)q;                                     // q in [0,15] exactly
        float p2 = __int_as_float(0x47000000 - (qi << 23));   // 2^(15-q), one IMAD
        float ei = fmaxf(floorf(__fmul_rn(z, p2)), 0.0f);
        val[i] = ei;
        lsum = __fadd_rn(lsum, ei);
    }

    // ---- row sum (5-step warp bfly) ----
#pragma unroll
    for (int o = 16; o > 0; o >>= 1)
        lsum = __fadd_rn(lsum, __shfl_xor_sync(0xffffffffu, lsum, o));

    const float factor = floorf(__fdiv_rn(4294967296.0f, lsum));  // per-row, keep exact
    // approx_threshold = floor(thr*256) * sum / 256 ; /256 exact -> *2^-8
    const float approx = __fmul_rn(__fmul_rn(thr_fl, lsum), 0.00390625f);

    // ---- quantized split output: select params first, quantize once ----
    float4* __restrict__ orow = reinterpret_cast<float4*>(out + row * ROW_N);
#pragma unroll
    for (int j = 0; j < V4_PER_LANE; j++) {
        float4 o4;
        float* op = &o4.x;
#pragma unroll
        for (int c = 0; c < 4; c++) {
            const float e      = val[4*j + c];
            const bool  isA    = (e <= approx);
            const float invDen = isA ? invDenA : invDenB;
            const float osel   = isA ? oA      : oB;
            const float cap    = isA ? posInf  : 255.0f;      // fminf(x,+INF)==x
            const float s = floorf(__fmul_rn(__fmul_rn(e, factor), invDen));
            op[c] = __fmul_rn(fminf(s, cap), osel);
        }
        __stcs(&orow[j * 32 + lane], o4);                     // streaming store
    }
}

extern "C" void kernel_launch(void* const* d_in, const int* in_sizes, int n_in,
                              void* d_out, int out_size)
{
    const float* x     = (const float*)d_in[0];
    const float* scale = (const float*)d_in[1];
    const float* thr   = (const float*)d_in[2];
    float* out         = (float*)d_out;

    const int rows = in_sizes[0] / ROW_N;                     // 32768
    const int ctas = (rows + ROWS_PER_CTA - 1) / ROWS_PER_CTA;
    qsplit_int_softmax_kernel<<<ctas, THREADS>>>(x, scale, thr, out, rows);
}